// round 6
// baseline (speedup 1.0000x reference)
#include <cuda_runtime.h>

#define NB   2048   // batch == ne == 2048
#define ND   128    // dims
#define TILE 64     // output tile edge
#define KCH  64     // dims per smem stage

// Scratch (allocation-free rule: __device__ globals)
__device__ float g_XT[ND * NB];   // transposed, attn-scaled inputs   [d][b]
__device__ float g_ET[ND * NB];   // transposed, attn-scaled exemplars[d][e]
__device__ float g_P[NB];         // -C * rowsum(attn*x) per batch row
__device__ float g_Q[NB];         // -C * rowsum(attn*e) per exemplar

// ---------------------------------------------------------------------------
// Prep: one launch, both matrices. 32x128 tile transpose through padded smem,
// coalesced LDG.128 and STG.128, attn-scaling + (-C)*rowsum fused.
// ---------------------------------------------------------------------------
__global__ __launch_bounds__(256) void prep2_kernel(
    const float* __restrict__ X, const float* __restrict__ E,
    const float* __restrict__ attn)
{
    __shared__ float a[ND];
    __shared__ float T[32][ND + 1];

    int bid = blockIdx.x;
    bool isE = bid >= 64;
    const float* src = isE ? E : X;
    float* dstT      = isE ? g_ET : g_XT;
    float* sums      = isE ? g_Q  : g_P;
    int rowbase = (bid & 63) * 32;

    int t = threadIdx.x;
    if (t < ND) a[t] = attn[t];
    __syncthreads();

    int r   = t >> 3;
    int seg = t & 7;
    const float4* srow = (const float4*)&src[(rowbase + r) * ND + seg * 16];
    float s = 0.0f;
    #pragma unroll
    for (int k = 0; k < 4; k++) {
        float4 v = srow[k];
        int d = seg * 16 + k * 4;
        v.x *= a[d + 0]; v.y *= a[d + 1]; v.z *= a[d + 2]; v.w *= a[d + 3];
        T[r][d + 0] = v.x; T[r][d + 1] = v.y;
        T[r][d + 2] = v.z; T[r][d + 3] = v.w;
        s += v.x + v.y + v.z + v.w;
    }
    s += __shfl_down_sync(0xffffffffu, s, 4);
    s += __shfl_down_sync(0xffffffffu, s, 2);
    s += __shfl_down_sync(0xffffffffu, s, 1);
    if (seg == 0) sums[rowbase + r] = -6.5f * s;
    __syncthreads();

    #pragma unroll
    for (int k = 0; k < 4; k++) {
        int o  = t + k * 256;
        int d  = o >> 3;
        int rg = o & 7;
        float4 v;
        v.x = T[rg * 4 + 0][d];
        v.y = T[rg * 4 + 1][d];
        v.z = T[rg * 4 + 2][d];
        v.w = T[rg * 4 + 3][d];
        *(float4*)&dstT[d * NB + rowbase + rg * 4] = v;
    }
}

// ---------------------------------------------------------------------------
// Main: 64x64 tile, 128 threads, 4x8 register micro-tile (rows x cols).
// tx = tid&7 -> 8 cols each; ty = tid>>3 -> 4 rows each.
// acc[b,e] = sum_d min(X'[d,b], E'[d,e]);  out = expf(P[b] + Q[e] + 13*acc)
// ---------------------------------------------------------------------------
__global__ __launch_bounds__(128, 6) void alcove_main(float* __restrict__ out)
{
    __shared__ float Xs[KCH * TILE];   // 16KB
    __shared__ float Es[KCH * TILE];   // 16KB

    int tid = threadIdx.x;        // 0..127
    int tx  = tid & 7;            // column group (8 cols)
    int ty  = tid >> 3;           // row group (4 rows), 0..15
    int rb  = blockIdx.y * TILE;
    int cb  = blockIdx.x * TILE;

    float acc[4][8];
    #pragma unroll
    for (int i = 0; i < 4; i++)
        #pragma unroll
        for (int j = 0; j < 8; j++)
            acc[i][j] = 0.0f;

    const float4* gx = (const float4*)g_XT;
    const float4* ge = (const float4*)g_ET;
    float4* xs4 = (float4*)Xs;
    float4* es4 = (float4*)Es;

    #pragma unroll 1
    for (int kb = 0; kb < ND / KCH; kb++) {
        // Load 64 d-rows x 64 floats per matrix = 1024 float4 each;
        // 128 threads x 8 float4. Half-warp reads 256B contiguous (LDG.128),
        // STS.128 conflict-free.
        #pragma unroll
        for (int k = 0; k < 8; k++) {
            int fi = tid + k * 128;
            int d  = fi >> 4;
            int q  = fi & 15;
            int gofs = (kb * KCH + d) * (NB / 4);
            xs4[d * (TILE / 4) + q] = gx[gofs + (rb >> 2) + q];
            es4[d * (TILE / 4) + q] = ge[gofs + (cb >> 2) + q];
        }
        __syncthreads();

        #pragma unroll 4
        for (int d = 0; d < KCH; d++) {
            float4 xv = *(const float4*)&Xs[d * TILE + ty * 4];
            float4 e0 = *(const float4*)&Es[d * TILE + tx * 8];
            float4 e1 = *(const float4*)&Es[d * TILE + tx * 8 + 4];
            float x[4] = {xv.x, xv.y, xv.z, xv.w};
            float e[8] = {e0.x, e0.y, e0.z, e0.w, e1.x, e1.y, e1.z, e1.w};
            #pragma unroll
            for (int i = 0; i < 4; i++)
                #pragma unroll
                for (int j = 0; j < 8; j++)
                    acc[i][j] += fminf(x[i], e[j]);   // FMNMX(alu)+FADD2(fma)
        }
        __syncthreads();
    }

    // Epilogue: out = exp(P + Q + 2C*acc), 2C = 13.
    float qv[8];
    #pragma unroll
    for (int j = 0; j < 8; j++) qv[j] = g_Q[cb + tx * 8 + j];

    #pragma unroll
    for (int i = 0; i < 4; i++) {
        int r = rb + ty * 4 + i;
        float p = g_P[r];
        float4 o0, o1;
        o0.x = __expf(fmaf(13.0f, acc[i][0], p + qv[0]));
        o0.y = __expf(fmaf(13.0f, acc[i][1], p + qv[1]));
        o0.z = __expf(fmaf(13.0f, acc[i][2], p + qv[2]));
        o0.w = __expf(fmaf(13.0f, acc[i][3], p + qv[3]));
        o1.x = __expf(fmaf(13.0f, acc[i][4], p + qv[4]));
        o1.y = __expf(fmaf(13.0f, acc[i][5], p + qv[5]));
        o1.z = __expf(fmaf(13.0f, acc[i][6], p + qv[6]));
        o1.w = __expf(fmaf(13.0f, acc[i][7], p + qv[7]));
        *(float4*)&out[r * NB + cb + tx * 8]     = o0;
        *(float4*)&out[r * NB + cb + tx * 8 + 4] = o1;
    }
}

// ---------------------------------------------------------------------------
extern "C" void kernel_launch(void* const* d_in, const int* in_sizes, int n_in,
                              void* d_out, int out_size)
{
    const float* inputs    = (const float*)d_in[0];
    const float* exemplars = (const float*)d_in[1];
    const float* attn      = (const float*)d_in[2];
    float* out = (float*)d_out;

    prep2_kernel<<<128, 256>>>(inputs, exemplars, attn);

    dim3 grid(NB / TILE, NB / TILE);   // 32 x 32 = 1024 tiles
    alcove_main<<<grid, 128>>>(out);
}

// round 7
// speedup vs baseline: 1.1641x; 1.1641x over previous
#include <cuda_runtime.h>

#define NB   2048   // batch == ne == 2048
#define ND   128    // dims
#define TILE 64     // output tile edge
#define KCH  64     // dims per smem stage

// Scratch (allocation-free rule: __device__ globals)
__device__ float g_XT[ND * NB];   // transposed, attn-scaled inputs   [d][b]
__device__ float g_ET[ND * NB];   // transposed, attn-scaled exemplars[d][e]
__device__ float g_P[NB];         // -C * rowsum(attn*x) per batch row
__device__ float g_Q[NB];         // -C * rowsum(attn*e) per exemplar

// ---------------------------------------------------------------------------
// Prep: one launch, both matrices. 32x128 tile transpose through padded smem,
// coalesced LDG.128 and STG.128, attn-scaling + (-C)*rowsum fused.
// ---------------------------------------------------------------------------
__global__ __launch_bounds__(256) void prep2_kernel(
    const float* __restrict__ X, const float* __restrict__ E,
    const float* __restrict__ attn)
{
    __shared__ float a[ND];
    __shared__ float T[32][ND + 1];

    int bid = blockIdx.x;
    bool isE = bid >= 64;
    const float* src = isE ? E : X;
    float* dstT      = isE ? g_ET : g_XT;
    float* sums      = isE ? g_Q  : g_P;
    int rowbase = (bid & 63) * 32;

    int t = threadIdx.x;
    if (t < ND) a[t] = attn[t];
    __syncthreads();

    int r   = t >> 3;
    int seg = t & 7;
    const float4* srow = (const float4*)&src[(rowbase + r) * ND + seg * 16];
    float s = 0.0f;
    #pragma unroll
    for (int k = 0; k < 4; k++) {
        float4 v = srow[k];
        int d = seg * 16 + k * 4;
        v.x *= a[d + 0]; v.y *= a[d + 1]; v.z *= a[d + 2]; v.w *= a[d + 3];
        T[r][d + 0] = v.x; T[r][d + 1] = v.y;
        T[r][d + 2] = v.z; T[r][d + 3] = v.w;
        s += v.x + v.y + v.z + v.w;
    }
    s += __shfl_down_sync(0xffffffffu, s, 4);
    s += __shfl_down_sync(0xffffffffu, s, 2);
    s += __shfl_down_sync(0xffffffffu, s, 1);
    if (seg == 0) sums[rowbase + r] = -6.5f * s;
    __syncthreads();

    #pragma unroll
    for (int k = 0; k < 4; k++) {
        int o  = t + k * 256;
        int d  = o >> 3;
        int rg = o & 7;
        float4 v;
        v.x = T[rg * 4 + 0][d];
        v.y = T[rg * 4 + 1][d];
        v.z = T[rg * 4 + 2][d];
        v.w = T[rg * 4 + 3][d];
        *(float4*)&dstT[d * NB + rowbase + rg * 4] = v;
    }
}

// ---------------------------------------------------------------------------
// Main: 64x64 tile, 256 threads, 4x4 micro-tile. Mixed-route accumulation:
//   cols 0..2: acc += min(u,v)     (FMNMX alu + packed FADD2 fma)
//   col  3   : acc += |u - v|      (SUB + FADD|.| both on fma pipe)
// balances alu/fma pipe load -> 1.5 cyc/term floor instead of 2.0.
// Epilogue: cols 0..2: exp(P+Q+13*acc);  col 3: exp(-6.5*acc).
// ---------------------------------------------------------------------------
__global__ __launch_bounds__(256, 4) void alcove_main(float* __restrict__ out)
{
    __shared__ float Xs[KCH * TILE];   // 16KB
    __shared__ float Es[KCH * TILE];   // 16KB

    int tid = threadIdx.x;
    int tx  = tid & 15;
    int ty  = tid >> 4;
    int rb  = blockIdx.y * TILE;
    int cb  = blockIdx.x * TILE;

    float acc[4][4];
    #pragma unroll
    for (int i = 0; i < 4; i++)
        #pragma unroll
        for (int j = 0; j < 4; j++)
            acc[i][j] = 0.0f;

    const float4* gx = (const float4*)g_XT;
    const float4* ge = (const float4*)g_ET;
    float4* xs4 = (float4*)Xs;
    float4* es4 = (float4*)Es;

    #pragma unroll 1
    for (int kb = 0; kb < ND / KCH; kb++) {
        #pragma unroll
        for (int k = 0; k < 4; k++) {
            int fi = tid + k * 256;
            int d  = fi >> 4;
            int q  = fi & 15;
            int gofs = (kb * KCH + d) * (NB / 4);
            xs4[d * (TILE / 4) + q] = gx[gofs + (rb >> 2) + q];
            es4[d * (TILE / 4) + q] = ge[gofs + (cb >> 2) + q];
        }
        __syncthreads();

        #pragma unroll 8
        for (int d = 0; d < KCH; d++) {
            float4 xv = *(const float4*)&Xs[d * TILE + ty * 4];
            float4 ev = *(const float4*)&Es[d * TILE + tx * 4];
            float x[4] = {xv.x, xv.y, xv.z, xv.w};
            #pragma unroll
            for (int i = 0; i < 4; i++) {
                acc[i][0] += fminf(x[i], ev.x);   // FMNMX (alu) + ADD2 (fma)
                acc[i][1] += fminf(x[i], ev.y);
                acc[i][2] += fminf(x[i], ev.z);
                acc[i][3] += fabsf(x[i] - ev.w);  // SUB + FADD|.| (fma only)
            }
        }
        __syncthreads();
    }

    // Epilogue. cols 0..2: exp(P + Q + 13*acc); col 3: exp(-6.5*acc).
    float q0 = g_Q[cb + tx * 4 + 0];
    float q1 = g_Q[cb + tx * 4 + 1];
    float q2 = g_Q[cb + tx * 4 + 2];
    #pragma unroll
    for (int i = 0; i < 4; i++) {
        int r = rb + ty * 4 + i;
        float p = g_P[r];
        float4 o;
        o.x = __expf(fmaf(13.0f, acc[i][0], p + q0));
        o.y = __expf(fmaf(13.0f, acc[i][1], p + q1));
        o.z = __expf(fmaf(13.0f, acc[i][2], p + q2));
        o.w = __expf(-6.5f * acc[i][3]);
        *(float4*)&out[r * NB + cb + tx * 4] = o;
    }
}

// ---------------------------------------------------------------------------
extern "C" void kernel_launch(void* const* d_in, const int* in_sizes, int n_in,
                              void* d_out, int out_size)
{
    const float* inputs    = (const float*)d_in[0];
    const float* exemplars = (const float*)d_in[1];
    const float* attn      = (const float*)d_in[2];
    float* out = (float*)d_out;

    prep2_kernel<<<128, 256>>>(inputs, exemplars, attn);

    dim3 grid(NB / TILE, NB / TILE);   // 32 x 32 = 1024 tiles
    alcove_main<<<grid, 256>>>(out);
}

// round 8
// speedup vs baseline: 1.1712x; 1.0061x over previous
#include <cuda_runtime.h>

#define NB   2048   // batch == ne == 2048
#define ND   128    // dims
#define TILE 64     // output tile edge
#define KCH  64     // dims per smem stage

// Scratch (allocation-free rule: __device__ globals)
__device__ float g_XT[ND * NB];   // transposed, attn-scaled inputs   [d][b]
__device__ float g_ET[ND * NB];   // transposed, attn-scaled exemplars[d][e]
__device__ float g_P[NB];         // -C * rowsum(attn*x) per batch row
__device__ float g_Q[NB];         // -C * rowsum(attn*e) per exemplar

// ---------------------------------------------------------------------------
// Prep: one launch, both matrices. 32x128 tile transpose through padded smem,
// coalesced LDG.128 and STG.128, attn-scaling + (-C)*rowsum fused.
// ---------------------------------------------------------------------------
__global__ __launch_bounds__(256) void prep2_kernel(
    const float* __restrict__ X, const float* __restrict__ E,
    const float* __restrict__ attn)
{
    __shared__ float a[ND];
    __shared__ float T[32][ND + 1];

    int bid = blockIdx.x;
    bool isE = bid >= 64;
    const float* src = isE ? E : X;
    float* dstT      = isE ? g_ET : g_XT;
    float* sums      = isE ? g_Q  : g_P;
    int rowbase = (bid & 63) * 32;

    int t = threadIdx.x;
    if (t < ND) a[t] = attn[t];
    __syncthreads();

    int r   = t >> 3;
    int seg = t & 7;
    const float4* srow = (const float4*)&src[(rowbase + r) * ND + seg * 16];
    float s = 0.0f;
    #pragma unroll
    for (int k = 0; k < 4; k++) {
        float4 v = srow[k];
        int d = seg * 16 + k * 4;
        v.x *= a[d + 0]; v.y *= a[d + 1]; v.z *= a[d + 2]; v.w *= a[d + 3];
        T[r][d + 0] = v.x; T[r][d + 1] = v.y;
        T[r][d + 2] = v.z; T[r][d + 3] = v.w;
        s += v.x + v.y + v.z + v.w;
    }
    s += __shfl_down_sync(0xffffffffu, s, 4);
    s += __shfl_down_sync(0xffffffffu, s, 2);
    s += __shfl_down_sync(0xffffffffu, s, 1);
    if (seg == 0) sums[rowbase + r] = -6.5f * s;
    __syncthreads();

    #pragma unroll
    for (int k = 0; k < 4; k++) {
        int o  = t + k * 256;
        int d  = o >> 3;
        int rg = o & 7;
        float4 v;
        v.x = T[rg * 4 + 0][d];
        v.y = T[rg * 4 + 1][d];
        v.z = T[rg * 4 + 2][d];
        v.w = T[rg * 4 + 3][d];
        *(float4*)&dstT[d * NB + rowbase + rg * 4] = v;
    }
}

// ---------------------------------------------------------------------------
// Main: 64x64 tile, 256 threads, 4x4 micro-tile. Mixed-route accumulation:
//   cols 0..2: acc += min(u,v)     (FMNMX alu + packed FADD2 fma)
//   col  3   : acc += |u - v|      (SUB + FADD|.| both on fma pipe)
// balances alu/fma pipe load -> 1.5 cyc/term floor instead of 2.0.
// Epilogue: cols 0..2: exp(P+Q+13*acc);  col 3: exp(-6.5*acc).
// ---------------------------------------------------------------------------
__global__ __launch_bounds__(256, 4) void alcove_main(float* __restrict__ out)
{
    __shared__ float Xs[KCH * TILE];   // 16KB
    __shared__ float Es[KCH * TILE];   // 16KB

    int tid = threadIdx.x;
    int tx  = tid & 15;
    int ty  = tid >> 4;
    int rb  = blockIdx.y * TILE;
    int cb  = blockIdx.x * TILE;

    float acc[4][4];
    #pragma unroll
    for (int i = 0; i < 4; i++)
        #pragma unroll
        for (int j = 0; j < 4; j++)
            acc[i][j] = 0.0f;

    const float4* gx = (const float4*)g_XT;
    const float4* ge = (const float4*)g_ET;
    float4* xs4 = (float4*)Xs;
    float4* es4 = (float4*)Es;

    #pragma unroll 1
    for (int kb = 0; kb < ND / KCH; kb++) {
        #pragma unroll
        for (int k = 0; k < 4; k++) {
            int fi = tid + k * 256;
            int d  = fi >> 4;
            int q  = fi & 15;
            int gofs = (kb * KCH + d) * (NB / 4);
            xs4[d * (TILE / 4) + q] = gx[gofs + (rb >> 2) + q];
            es4[d * (TILE / 4) + q] = ge[gofs + (cb >> 2) + q];
        }
        __syncthreads();

        #pragma unroll 8
        for (int d = 0; d < KCH; d++) {
            float4 xv = *(const float4*)&Xs[d * TILE + ty * 4];
            float4 ev = *(const float4*)&Es[d * TILE + tx * 4];
            float x[4] = {xv.x, xv.y, xv.z, xv.w};
            #pragma unroll
            for (int i = 0; i < 4; i++) {
                acc[i][0] += fminf(x[i], ev.x);   // FMNMX (alu) + ADD2 (fma)
                acc[i][1] += fminf(x[i], ev.y);
                acc[i][2] += fminf(x[i], ev.z);
                acc[i][3] += fabsf(x[i] - ev.w);  // SUB + FADD|.| (fma only)
            }
        }
        __syncthreads();
    }

    // Epilogue. cols 0..2: exp(P + Q + 13*acc); col 3: exp(-6.5*acc).
    float q0 = g_Q[cb + tx * 4 + 0];
    float q1 = g_Q[cb + tx * 4 + 1];
    float q2 = g_Q[cb + tx * 4 + 2];
    #pragma unroll
    for (int i = 0; i < 4; i++) {
        int r = rb + ty * 4 + i;
        float p = g_P[r];
        float4 o;
        o.x = __expf(fmaf(13.0f, acc[i][0], p + q0));
        o.y = __expf(fmaf(13.0f, acc[i][1], p + q1));
        o.z = __expf(fmaf(13.0f, acc[i][2], p + q2));
        o.w = __expf(-6.5f * acc[i][3]);
        *(float4*)&out[r * NB + cb + tx * 4] = o;
    }
}

// ---------------------------------------------------------------------------
extern "C" void kernel_launch(void* const* d_in, const int* in_sizes, int n_in,
                              void* d_out, int out_size)
{
    const float* inputs    = (const float*)d_in[0];
    const float* exemplars = (const float*)d_in[1];
    const float* attn      = (const float*)d_in[2];
    float* out = (float*)d_out;

    prep2_kernel<<<128, 256>>>(inputs, exemplars, attn);

    dim3 grid(NB / TILE, NB / TILE);   // 32 x 32 = 1024 tiles
    alcove_main<<<grid, 256>>>(out);
}